// round 16
// baseline (speedup 1.0000x reference)
#include <cuda_runtime.h>
#include <cuda_fp16.h>
#include <math.h>
#include <stdint.h>

// ---------------- problem constants ----------------
#define Bsz 8192
#define Dm  1024
#define Ff  4096
#define Ssup 4
#define Hh  4
#define HD  256
#define BHALF (Bsz / 2)

// ---------------- GEMM tiling ----------------
#define BM 128
#define NST 3

// ---------------- scratch (device globals) ----------------
__device__ __half g_xh [(size_t)Bsz*Dm];
__device__ __half g_w1 [(size_t)Ssup*Ff*Dm];   // [s][f][d] (transposed)
__device__ __half g_w2 [(size_t)Ssup*Dm*Ff];   // [s][d][f]
__device__ __half g_wq [(size_t)Dm*Dm];        // transposed [n][k]
__device__ __half g_wk2[(size_t)Dm*Dm];        // straight [m][d]
__device__ __half g_wv [(size_t)Dm*Dm];        // transposed
__device__ __half g_wo [(size_t)Dm*Dm];        // transposed
__device__ __half g_hh [(size_t)Ssup*Bsz*Ff];                             // h single fp16
__device__ __half g_yh [(size_t)Ssup*Bsz*Dm],  g_yl [(size_t)Ssup*Bsz*Dm];
__device__ __half g_qh [(size_t)Bsz*Dm];
__device__ __half g_zh [(size_t)Hh*Bsz*Dm];    // [h][b][m]
__device__ __half g_oh [(size_t)Bsz*Dm];
__device__ float g_t [(size_t)Hh*Bsz*Dm];      // [h][b][m]

// ---------------- asm helpers (generic-target PTX, sm_80+) ----------------
__device__ __forceinline__ uint32_t smem_u32(const void* p) {
    uint32_t a;
    asm("{ .reg .u64 t; cvta.to.shared.u64 t, %1; cvt.u32.u64 %0, t; }" : "=r"(a) : "l"(p));
    return a;
}
__device__ __forceinline__ void cp16(uint32_t dst, const void* src) {
    asm volatile("cp.async.cg.shared.global [%0], [%1], 16;" :: "r"(dst), "l"(src));
}
#define CP_COMMIT() asm volatile("cp.async.commit_group;" ::: "memory")
#define CP_WAIT(n)  asm volatile("cp.async.wait_group %0;" :: "n"(n) : "memory")
#define LDSM4(r, a) asm volatile("ldmatrix.sync.aligned.m8n8.x4.shared.b16 {%0,%1,%2,%3}, [%4];" \
    : "=r"((r)[0]), "=r"((r)[1]), "=r"((r)[2]), "=r"((r)[3]) : "r"(a))
#define MMA16816(ac, a, b0, b1) \
    asm volatile("mma.sync.aligned.m16n8k16.row.col.f32.f16.f16.f32 " \
        "{%0,%1,%2,%3}, {%4,%5,%6,%7}, {%8,%9}, {%0,%1,%2,%3};" \
        : "+f"((ac)[0]), "+f"((ac)[1]), "+f"((ac)[2]), "+f"((ac)[3]) \
        : "r"((a)[0]), "r"((a)[1]), "r"((a)[2]), "r"((a)[3]), "r"(b0), "r"(b1))

__device__ __forceinline__ float gelu_exact(float x) {
    return 0.5f * x * (1.0f + erff(x * 0.70710678118654752440f));
}
__device__ __forceinline__ void split2(float v, __half* h, __half* l) {
    __half hb = __float2half(v);
    *h = hb;
    *l = __float2half(v - __half2float(hb));
}
// 16B-chunk swizzle, parameterized on chunks-per-row (row bytes = CPR*16)
template <int CPR>
__device__ __forceinline__ uint32_t swzT(int row, int c16) {
    return (uint32_t)(row * CPR + (c16 ^ (row & 7))) * 16u;
}

// ---------------- conversion / build kernels ----------------
__global__ void half_arr(const float* __restrict__ in, __half* __restrict__ o, size_t n) {
    size_t i = (size_t)blockIdx.x * blockDim.x + threadIdx.x;
    if (i < n) o[i] = __float2half(in[i]);
}

__global__ __launch_bounds__(256)
void ttile_w(const float* __restrict__ wq, const float* __restrict__ wv,
             const float* __restrict__ wo,
             __half* __restrict__ oq, __half* __restrict__ ov, __half* __restrict__ oo)
{
    __shared__ float tile[32][33];
    const float* w = blockIdx.z == 0 ? wq : (blockIdx.z == 1 ? wv : wo);
    __half* o      = blockIdx.z == 0 ? oq : (blockIdx.z == 1 ? ov : oo);
    const int bx = blockIdx.x * 32, by = blockIdx.y * 32;
    const int tx = threadIdx.x & 31, ty = threadIdx.x >> 5;  // 32x8
#pragma unroll
    for (int j = 0; j < 4; j++)
        tile[ty + j * 8][tx] = w[(size_t)(by + ty + j * 8) * Dm + bx + tx];
    __syncthreads();
#pragma unroll
    for (int j = 0; j < 4; j++)
        o[(size_t)(bx + ty + j * 8) * Dm + by + tx] = __float2half(tile[tx][ty + j * 8]);
}

#define W1_SMEM ((16*32*17 + 512) * 4)
__global__ __launch_bounds__(256)
void build_w1_tiled(const float* __restrict__ g1a, const float* __restrict__ g1b,
                    __half* __restrict__ o)
{
    extern __shared__ float dsm[];
    float* Bs = dsm;                 // [(r*32+i2)*17 + o2l]
    float* As = dsm + 16 * 32 * 17;  // [i1][r]
    const int tid = threadIdx.x;
    const int o1 = blockIdx.x, q = blockIdx.y, s = blockIdx.z;

    for (int idx = tid; idx < 8192; idx += 256) {
        int r = idx >> 9, i2 = (idx >> 4) & 31, o2l = idx & 15;
        Bs[(r * 32 + i2) * 17 + o2l] =
            g1b[(size_t)s * 32768 + (size_t)r * 2048 + i2 * 64 + q * 16 + o2l];
    }
    for (int idx = tid; idx < 512; idx += 256) {
        int i1 = idx >> 4, r = idx & 15;
        As[idx] = g1a[(((size_t)s * 32 + i1) * 64 + o1) * 16 + r];
    }
    __syncthreads();

    const size_t ob = ((size_t)s * Ff + (size_t)o1 * 64 + q * 16) * Dm;
#pragma unroll 4
    for (int it = 0; it < 64; it++) {
        int idx = tid + (it << 8);
        int o2l = idx >> 10, d = idx & 1023;
        int i1 = d >> 5, i2 = d & 31;
        const float* ap = As + i1 * 16;
        const float* bp = Bs + i2 * 17 + o2l;
        float sum = 0.f;
#pragma unroll
        for (int r = 0; r < 16; r++) sum += ap[r] * bp[r * 544];
        o[ob + (size_t)o2l * Dm + d] = __float2half(sum);
    }
}

#define W2_SMEM ((16*16*33 + 512) * 4)
__global__ __launch_bounds__(256)
void build_w2_tiled(const float* __restrict__ g2a, const float* __restrict__ g2b,
                    __half* __restrict__ o)
{
    extern __shared__ float dsm[];
    float* Bs = dsm;                 // [(r*16+o2l)*33 + i2]
    float* As = dsm + 16 * 16 * 33;  // [i1][r]
    const int tid = threadIdx.x;
    const int o1 = blockIdx.x, q = blockIdx.y, s = blockIdx.z;

    for (int idx = tid; idx < 8192; idx += 256) {
        int r = idx >> 9, o2l = (idx >> 5) & 15, i2 = idx & 31;
        Bs[(r * 16 + o2l) * 33 + i2] =
            g2b[(size_t)s * 32768 + (size_t)r * 2048 + (q * 16 + o2l) * 32 + i2];
    }
    for (int idx = tid; idx < 512; idx += 256) {
        int i1 = idx >> 4, r = idx & 15;
        As[idx] = g2a[(((size_t)s * 64 + o1) * 32 + i1) * 16 + r];
    }
    __syncthreads();

    const size_t ob = (size_t)s * Dm * Ff + (size_t)o1 * 64 + q * 16;
#pragma unroll 4
    for (int it = 0; it < 64; it++) {
        int idx = tid + (it << 8);
        int d = idx >> 4, o2l = idx & 15;
        int i1 = d >> 5, i2 = d & 31;
        const float* ap = As + i1 * 16;
        const float* bp = Bs + o2l * 33 + i2;
        float sum = 0.f;
#pragma unroll
        for (int r = 0; r < 16; r++) sum += ap[r] * bp[r * 528];
        o[ob + (size_t)d * Ff + o2l] = __float2half(sum);
    }
}

// ---------------- fp16 HMMA GEMM body (templated on BN, BK) ----------------
// EPI: 0 split, 1 gelu+single, 2 bias+fp32, 4 fp32, 5 bias+single
template <int EPI, int XA, int BNT, int BKT>
__device__ __forceinline__
void gemm_body(const __half* __restrict__ Ah, const __half* __restrict__ Al,
               int lda, size_t aBS,
               const __half* __restrict__ Bh, int ldb, size_t bBS,
               int K, int ldc, size_t cBS,
               float* __restrict__ Cf,
               __half* __restrict__ Chi, __half* __restrict__ Clo,
               const float* __restrict__ bias, size_t biasBS)
{
    constexpr int CPR = BKT / 8;                 // 16B chunks per row
    constexpr int RPP = 256 / CPR;               // rows per fill pass
    constexpr uint32_t A_Bt = BM * BKT * 2;
    constexpr uint32_t B_Bt = BNT * BKT * 2;
    constexpr uint32_t STG  = XA * A_Bt + B_Bt;
    constexpr int P = BNT / 64;
    extern __shared__ char smem[];
    const uint32_t sb = smem_u32(smem);
    const int tid = threadIdx.x, wid = tid >> 5, lane = tid & 31;
    const int zz = blockIdx.z;
    const int m0 = blockIdx.y * BM, n0 = blockIdx.x * BNT;

    const __half* pAh = Ah + (size_t)zz * aBS;
    const __half* pAl = (XA == 2) ? Al + (size_t)zz * aBS : nullptr;
    const __half* pBh = Bh + (size_t)zz * bBS;

    const int mwarp = (wid & 1) * 64;
    const int nwarp = (wid >> 1) * (BNT / 4);

    float acc[4][2 * P][4];
#pragma unroll
    for (int i = 0; i < 4; i++)
#pragma unroll
        for (int j = 0; j < 2 * P; j++)
#pragma unroll
            for (int c = 0; c < 4; c++) acc[i][j][c] = 0.f;

    const int nk = K / BKT;
    const int fr = tid / CPR, fc = tid % CPR;

    auto fill = [&](int kt, int st) {
        const int k0 = kt * BKT;
        const uint32_t base = sb + st * STG;
#pragma unroll
        for (int i = 0; i < BM / RPP; i++) {
            int r = fr + i * RPP;
            cp16(base + swzT<CPR>(r, fc), pAh + (size_t)(m0 + r) * lda + k0 + fc * 8);
            if (XA == 2)
                cp16(base + A_Bt + swzT<CPR>(r, fc), pAl + (size_t)(m0 + r) * lda + k0 + fc * 8);
        }
#pragma unroll
        for (int i = 0; i < BNT / RPP; i++) {
            int r = fr + i * RPP;
            cp16(base + XA*A_Bt + swzT<CPR>(r, fc), pBh + (size_t)(n0 + r) * ldb + k0 + fc * 8);
        }
        CP_COMMIT();
    };

    fill(0, 0);
    if (nk > 1) fill(1, 1);

    const int ra = lane & 15, ca = lane >> 4;
    const int gb = lane >> 3, rb = lane & 7;

    for (int kt = 0; kt < nk; kt++) {
        if (kt + 1 >= nk) { CP_WAIT(0); } else { CP_WAIT(1); }
        __syncthreads();
        if (kt + 2 < nk) fill(kt + 2, (kt + 2) % NST);

        const uint32_t base = sb + (kt % NST) * STG;
        const uint32_t sAh = base, sAl = base + A_Bt;
        const uint32_t sBh = base + XA * A_Bt;

#pragma unroll
        for (int kk = 0; kk < BKT / 16; kk++) {
            uint32_t ah[4][4], al[4][4];
#pragma unroll
            for (int mt = 0; mt < 4; mt++) {
                uint32_t off = swzT<CPR>(mwarp + mt * 16 + ra, kk * 2 + ca);
                LDSM4(ah[mt], sAh + off);
                if (XA == 2) LDSM4(al[mt], sAl + off);
            }
#pragma unroll
            for (int p = 0; p < P; p++) {
                uint32_t bh[4];
                uint32_t off = swzT<CPR>(nwarp + p * 16 + (gb & 1) * 8 + rb, kk * 2 + (gb >> 1));
                LDSM4(bh, sBh + off);
#pragma unroll
                for (int mt = 0; mt < 4; mt++) {
                    MMA16816(acc[mt][2*p],   ah[mt], bh[0], bh[2]);
                    MMA16816(acc[mt][2*p+1], ah[mt], bh[1], bh[3]);
                    if (XA == 2) {
                        MMA16816(acc[mt][2*p],   al[mt], bh[0], bh[2]);
                        MMA16816(acc[mt][2*p+1], al[mt], bh[1], bh[3]);
                    }
                }
            }
        }
    }

    float* Cfp = Cf ? Cf + (size_t)zz * cBS : nullptr;
    __half* Chp = Chi ? Chi + (size_t)zz * cBS : nullptr;
    __half* Clp = Clo ? Clo + (size_t)zz * cBS : nullptr;
    const float* bp = bias ? bias + (size_t)zz * biasBS : nullptr;
    const int g4 = lane >> 2, q2 = (lane & 3) * 2;

#pragma unroll
    for (int mt = 0; mt < 4; mt++) {
#pragma unroll
        for (int nt = 0; nt < 2 * P; nt++) {
            int r0 = m0 + mwarp + mt * 16 + g4;
            int c  = n0 + nwarp + nt * 8 + q2;
#pragma unroll
            for (int half = 0; half < 2; half++) {
                int rr = r0 + half * 8;
                float v0 = acc[mt][nt][half * 2 + 0];
                float v1 = acc[mt][nt][half * 2 + 1];
                size_t off = (size_t)rr * ldc + c;
                if (EPI == 2) {
                    *reinterpret_cast<float2*>(&Cfp[off]) =
                        make_float2(v0 + bp[c], v1 + bp[c + 1]);
                } else if (EPI == 4) {
                    *reinterpret_cast<float2*>(&Cfp[off]) = make_float2(v0, v1);
                } else if (EPI == 1) {
                    __half2 h2;
                    h2.x = __float2half(gelu_exact(v0));
                    h2.y = __float2half(gelu_exact(v1));
                    *reinterpret_cast<__half2*>(&Chp[off]) = h2;
                } else if (EPI == 5) {
                    __half2 h2;
                    h2.x = __float2half(v0 + bp[c]);
                    h2.y = __float2half(v1 + bp[c + 1]);
                    *reinterpret_cast<__half2*>(&Chp[off]) = h2;
                } else {  // EPI == 0: split
                    __half2 h2, l2;
                    split2(v0, &h2.x, &l2.x);
                    split2(v1, &h2.y, &l2.y);
                    *reinterpret_cast<__half2*>(&Chp[off]) = h2;
                    *reinterpret_cast<__half2*>(&Clp[off]) = l2;
                }
            }
        }
    }
}

// small-GEMM shell: BN=256, BK=64, occ1
template <int EPI, int XA>
__global__ __launch_bounds__(256, 1)
void mma_gemm(const __half* __restrict__ Ah, const __half* __restrict__ Al,
              int lda, size_t aBS,
              const __half* __restrict__ Bh, int ldb, size_t bBS,
              int K, int ldc, size_t cBS,
              float* __restrict__ Cf,
              __half* __restrict__ Chi, __half* __restrict__ Clo,
              const float* __restrict__ bias, size_t biasBS)
{
    gemm_body<EPI, XA, 256, 64>(Ah, Al, lda, aBS, Bh, ldb, bBS, K, ldc, cBS,
                                Cf, Chi, Clo, bias, biasBS);
}

// FFN shell: BN=128, BK=128, occ1 (halved sync count)
template <int EPI, int XA>
__global__ __launch_bounds__(256, 1)
void ffn_gemm(const __half* __restrict__ Ah, const __half* __restrict__ Al,
              int lda, size_t aBS,
              const __half* __restrict__ Bh, int ldb, size_t bBS,
              int K, int ldc, size_t cBS,
              float* __restrict__ Cf,
              __half* __restrict__ Chi, __half* __restrict__ Clo,
              const float* __restrict__ bias, size_t biasBS)
{
    gemm_body<EPI, XA, 128, 128>(Ah, Al, lda, aBS, Bh, ldb, bBS, K, ldc, cBS,
                                 Cf, Chi, Clo, bias, biasBS);
}

// ---------------- attention collapse: scores, softmax, z ----------------
// pointers may be pre-offset by a half-batch (offD); indexing uses full Bsz strides
__global__ __launch_bounds__(256)
void attn_collapse(const __half* __restrict__ qh,
                   const float* __restrict__ t,
                   const __half* __restrict__ yh, const __half* __restrict__ yl,
                   const float* __restrict__ bk,
                   __half* __restrict__ zh)
{
    const int b = blockIdx.x, tid = threadIdx.x;
    const int wid = tid >> 5, lane = tid & 31;
    __shared__ float ys[Ssup][Dm];
    __shared__ float sc[16], qb[Hh], attn[16];

#pragma unroll
    for (int it = 0; it < 8; it++) {
        int idx = tid + it * 256;
        int s = idx >> 9, mm = idx & 511;
        size_t g = ((size_t)s * Bsz + b) * Dm + mm * 2;
        __half2 h2 = *reinterpret_cast<const __half2*>(&yh[g]);
        __half2 l2 = *reinterpret_cast<const __half2*>(&yl[g]);
        ys[s][mm * 2]     = __half2float(h2.x) + __half2float(l2.x);
        ys[s][mm * 2 + 1] = __half2float(h2.y) + __half2float(l2.y);
    }
    if (wid < Hh) {
        float sum = 0.f;
        for (int j = lane; j < HD; j += 32) {
            size_t g = (size_t)b * Dm + wid * HD + j;
            sum = fmaf(__half2float(qh[g]), bk[wid * HD + j], sum);
        }
#pragma unroll
        for (int o = 16; o; o >>= 1) sum += __shfl_xor_sync(0xffffffffu, sum, o);
        if (lane == 0) qb[wid] = sum;
    }
    __syncthreads();

#pragma unroll
    for (int i = 0; i < 2; i++) {
        int p = wid * 2 + i;
        int h = p >> 2, s = p & 3;
        const float* tp = t + ((size_t)h * Bsz + b) * Dm;
        float sum = 0.f;
        for (int m = lane; m < Dm; m += 32) sum = fmaf(ys[s][m], tp[m], sum);
#pragma unroll
        for (int o = 16; o; o >>= 1) sum += __shfl_xor_sync(0xffffffffu, sum, o);
        if (lane == 0) sc[p] = sum;
    }
    __syncthreads();

    if (tid < Hh) {
        int h = tid;
        float s0 = (sc[h*4+0] + qb[h]) * 0.0625f;
        float s1 = (sc[h*4+1] + qb[h]) * 0.0625f;
        float s2 = (sc[h*4+2] + qb[h]) * 0.0625f;
        float s3 = (sc[h*4+3] + qb[h]) * 0.0625f;
        float m = fmaxf(fmaxf(s0, s1), fmaxf(s2, s3));
        float e0 = expf(s0-m), e1 = expf(s1-m), e2 = expf(s2-m), e3 = expf(s3-m);
        float inv = 1.f / (e0 + e1 + e2 + e3);
        attn[h*4+0] = e0*inv; attn[h*4+1] = e1*inv;
        attn[h*4+2] = e2*inv; attn[h*4+3] = e3*inv;
    }
    __syncthreads();

#pragma unroll
    for (int it = 0; it < 8; it++) {
        int idx = tid + it * 256;
        int h = idx >> 9, mm = idx & 511;
        int m = mm * 2;
        float a0 = attn[h*4+0], a1 = attn[h*4+1], a2 = attn[h*4+2], a3 = attn[h*4+3];
        float z0 = a0*ys[0][m]   + a1*ys[1][m]   + a2*ys[2][m]   + a3*ys[3][m];
        float z1 = a0*ys[0][m+1] + a1*ys[1][m+1] + a2*ys[2][m+1] + a3*ys[3][m+1];
        size_t g = ((size_t)h * Bsz + b) * Dm + m;
        __half2 z2;
        z2.x = __float2half(z0);
        z2.y = __float2half(z1);
        *reinterpret_cast<__half2*>(&zh[g]) = z2;
    }
}

// ---------------- launch ----------------
extern "C" void kernel_launch(void* const* d_in, const int* in_sizes, int n_in,
                              void* d_out, int out_size)
{
    const float* x   = (const float*)d_in[0];
    const float* g1a = (const float*)d_in[1];
    const float* g1b = (const float*)d_in[2];
    const float* g2a = (const float*)d_in[3];
    const float* g2b = (const float*)d_in[4];
    const float* wq  = (const float*)d_in[5];
    const float* bq  = (const float*)d_in[6];
    const float* wk  = (const float*)d_in[7];
    const float* bk  = (const float*)d_in[8];
    const float* wv  = (const float*)d_in[9];
    const float* bv  = (const float*)d_in[10];
    const float* wo  = (const float*)d_in[11];
    const float* bo  = (const float*)d_in[12];
    float* out = (float*)d_out;

    __half *xh,*w1,*w2,*wqp,*wk2,*wvp,*wop,*hh,*yh,*yl,*qh,*zh,*oh;
    float *t;
    cudaGetSymbolAddress((void**)&xh, g_xh);
    cudaGetSymbolAddress((void**)&w1, g_w1);   cudaGetSymbolAddress((void**)&w2, g_w2);
    cudaGetSymbolAddress((void**)&wqp, g_wq);  cudaGetSymbolAddress((void**)&wk2, g_wk2);
    cudaGetSymbolAddress((void**)&wvp, g_wv);  cudaGetSymbolAddress((void**)&wop, g_wo);
    cudaGetSymbolAddress((void**)&hh, g_hh);
    cudaGetSymbolAddress((void**)&yh, g_yh);   cudaGetSymbolAddress((void**)&yl, g_yl);
    cudaGetSymbolAddress((void**)&qh, g_qh);
    cudaGetSymbolAddress((void**)&zh, g_zh);
    cudaGetSymbolAddress((void**)&oh, g_oh);
    cudaGetSymbolAddress((void**)&t, g_t);

    const int SM1 = NST * (BM*64*2 + 256*64*2);    // 147456 (small GEMMs, BK=64, BN=256)
    const int SMF = NST * (BM*128*2 + 128*128*2);  // 196608 (FFN, BK=128, BN=128)
    cudaFuncSetAttribute((const void*)ffn_gemm<1,1>, cudaFuncAttributeMaxDynamicSharedMemorySize, SMF);
    cudaFuncSetAttribute((const void*)ffn_gemm<0,1>, cudaFuncAttributeMaxDynamicSharedMemorySize, SMF);
    cudaFuncSetAttribute((const void*)mma_gemm<5,1>, cudaFuncAttributeMaxDynamicSharedMemorySize, SM1);
    cudaFuncSetAttribute((const void*)mma_gemm<4,1>, cudaFuncAttributeMaxDynamicSharedMemorySize, SM1);
    cudaFuncSetAttribute((const void*)mma_gemm<2,1>, cudaFuncAttributeMaxDynamicSharedMemorySize, SM1);
    cudaFuncSetAttribute((const void*)build_w1_tiled, cudaFuncAttributeMaxDynamicSharedMemorySize, W1_SMEM);
    cudaFuncSetAttribute((const void*)build_w2_tiled, cudaFuncAttributeMaxDynamicSharedMemorySize, W2_SMEM);

    const size_t sBD = (size_t)Bsz * Dm, sBF = (size_t)Bsz * Ff;
    const size_t sDD = (size_t)Dm * Dm, sFD = (size_t)Ff * Dm;
    const size_t offH = (size_t)BHALF * Ff;
    const size_t offD = (size_t)BHALF * Dm;

    // streams: s1 = q/t chain, s2 = build_w2, s3 = tail upper-half. Fallback: all on 0.
    cudaStream_t s1 = 0, s2 = 0, s3 = 0;
    cudaEvent_t evX = 0, evJ = 0, evW2 = 0, evY0 = 0, evT0 = 0;
    bool forked = (cudaStreamCreateWithFlags(&s1, cudaStreamNonBlocking) == cudaSuccess);
    if (forked && cudaStreamCreateWithFlags(&s2, cudaStreamNonBlocking) != cudaSuccess) {
        cudaStreamDestroy(s1); s1 = 0; forked = false;
    }
    if (forked && cudaStreamCreateWithFlags(&s3, cudaStreamNonBlocking) != cudaSuccess) {
        cudaStreamDestroy(s1); cudaStreamDestroy(s2); s1 = s2 = 0; forked = false;
    }
    if (forked && (cudaEventCreateWithFlags(&evX, cudaEventDisableTiming) != cudaSuccess ||
                   cudaEventCreateWithFlags(&evJ, cudaEventDisableTiming) != cudaSuccess ||
                   cudaEventCreateWithFlags(&evW2, cudaEventDisableTiming) != cudaSuccess ||
                   cudaEventCreateWithFlags(&evY0, cudaEventDisableTiming) != cudaSuccess ||
                   cudaEventCreateWithFlags(&evT0, cudaEventDisableTiming) != cudaSuccess)) {
        if (evX) cudaEventDestroy(evX);
        if (evJ) cudaEventDestroy(evJ);
        if (evW2) cudaEventDestroy(evW2);
        if (evY0) cudaEventDestroy(evY0);
        if (evT0) cudaEventDestroy(evT0);
        cudaStreamDestroy(s1); cudaStreamDestroy(s2); cudaStreamDestroy(s3);
        s1 = s2 = s3 = 0; evX = evJ = evW2 = evY0 = evT0 = 0; forked = false;
    }

    // main: x -> fp16
    half_arr<<<(Bsz * Dm) / 256, 256>>>(x, xh, sBD);
    if (forked) {
        cudaEventRecord(evX, 0);
        cudaStreamWaitEvent(s1, evX, 0);
        cudaStreamWaitEvent(s2, evX, 0);
        cudaStreamWaitEvent(s3, evX, 0);
    }

    // s2: w2 build
    build_w2_tiled<<<dim3(64, 4, Ssup), 256, W2_SMEM, s2>>>(g2a, g2b, w2);
    if (forked) cudaEventRecord(evW2, s2);

    // s1: attention-path weight preps, then q -> t
    ttile_w<<<dim3(32, 32, 3), 256, 0, s1>>>(wq, wv, wo, wqp, wvp, wop);
    half_arr<<<(Dm * Dm) / 256, 256, 0, s1>>>(wk, wk2, sDD);
    mma_gemm<5,1><<<dim3(Dm/256, Bsz/BM, 1), 256, SM1, s1>>>(
        xh, nullptr, Dm, 0, wqp, Dm, 0, Dm, Dm, 0,
        nullptr, qh, nullptr, bq, 0);
    mma_gemm<4,1><<<dim3(Dm/256, Bsz/BM, Hh), 256, SM1, s1>>>(
        qh, nullptr, Dm, HD, wk2, Dm, HD, HD, Dm, sBD,
        t, nullptr, nullptr, nullptr, 0);
    if (forked) cudaEventRecord(evJ, s1);

    // main: w1 build, FFN1 (full B, BK=128)
    build_w1_tiled<<<dim3(64, 4, Ssup), 256, W1_SMEM>>>(g1a, g1b, w1);
    ffn_gemm<1,1><<<dim3(Ff/128, Bsz/BM, Ssup), 256, SMF>>>(
        xh, nullptr, Dm, 0, w1, Dm, sFD, Dm, Ff, sBF,
        nullptr, hh, nullptr, nullptr, 0);

    // main: FFN2 UPPER half first (rows [BHALF, Bsz)) — matches the s3 tail below
    if (forked) cudaStreamWaitEvent(0, evW2, 0);
    ffn_gemm<0,1><<<dim3(Dm/128, BHALF/BM, Ssup), 256, SMF>>>(
        hh + offH, nullptr, Ff, sBF, w2, Ff, (size_t)Dm*Ff, Ff, Dm, sBD,
        nullptr, yh + offD, yl + offD, nullptr, 0);
    if (forked) cudaEventRecord(evY0, 0);

    // s3: tail for the UPPER half (runs beside FFN2 lower half)
    if (forked) {
        cudaStreamWaitEvent(s3, evY0, 0);
        cudaStreamWaitEvent(s3, evJ, 0);
    }
    attn_collapse<<<BHALF, 256, 0, s3>>>(qh + offD, t + offD, yh + offD, yl + offD, bk, zh + offD);
    mma_gemm<5,1><<<dim3(1, BHALF/BM, Hh), 256, SM1, s3>>>(
        zh + offD, nullptr, Dm, sBD, wvp, Dm, (size_t)HD*Dm, Dm, Dm, (size_t)HD,
        nullptr, oh + offD, nullptr, bv, HD);
    mma_gemm<2,1><<<dim3(Dm/256, BHALF/BM, 1), 256, SM1, s3>>>(
        oh + offD, nullptr, Dm, 0, wop, Dm, 0, Dm, Dm, 0,
        out + offD, nullptr, nullptr, bo, 0);
    if (forked) cudaEventRecord(evT0, s3);

    // main: FFN2 LOWER half (rows [0, BHALF))
    ffn_gemm<0,1><<<dim3(Dm/128, BHALF/BM, Ssup), 256, SMF>>>(
        hh, nullptr, Ff, sBF, w2, Ff, (size_t)Dm*Ff, Ff, Dm, sBD,
        nullptr, yh, yl, nullptr, 0);

    // main: tail for the LOWER half
    if (forked) cudaStreamWaitEvent(0, evJ, 0);
    attn_collapse<<<BHALF, 256>>>(qh, t, yh, yl, bk, zh);
    mma_gemm<5,1><<<dim3(1, BHALF/BM, Hh), 256, SM1>>>(
        zh, nullptr, Dm, sBD, wvp, Dm, (size_t)HD*Dm, Dm, Dm, (size_t)HD,
        nullptr, oh, nullptr, bv, HD);
    mma_gemm<2,1><<<dim3(Dm/256, BHALF/BM, 1), 256, SM1>>>(
        oh, nullptr, Dm, 0, wop, Dm, 0, Dm, Dm, 0,
        out, nullptr, nullptr, bo, 0);

    // join s3 back into origin before capture ends
    if (forked) cudaStreamWaitEvent(0, evT0, 0);

    if (forked) {
        cudaEventDestroy(evX);
        cudaEventDestroy(evJ);
        cudaEventDestroy(evW2);
        cudaEventDestroy(evY0);
        cudaEventDestroy(evT0);
        cudaStreamDestroy(s1);
        cudaStreamDestroy(s2);
        cudaStreamDestroy(s3);
    }
}

// round 17
// speedup vs baseline: 1.1149x; 1.1149x over previous
#include <cuda_runtime.h>
#include <cuda_fp16.h>
#include <math.h>
#include <stdint.h>

// ---------------- problem constants ----------------
#define Bsz 8192
#define Dm  1024
#define Ff  4096
#define Ssup 4
#define Hh  4
#define HD  256
#define BHALF (Bsz / 2)

// ---------------- GEMM tiling ----------------
#define BM 128
#define BK 64                    // fp16 elems per k-tile (128B rows)
#define NST 3
#define A_B   (BM * BK * 2)      // 16384 bytes per A matrix

// ---------------- scratch (device globals) ----------------
__device__ __half g_xh [(size_t)Bsz*Dm];
__device__ __half g_w1 [(size_t)Ssup*Ff*Dm];   // [s][f][d] (transposed)
__device__ __half g_w2 [(size_t)Ssup*Dm*Ff];   // [s][d][f]
__device__ __half g_wq [(size_t)Dm*Dm];        // transposed [n][k]
__device__ __half g_wk2[(size_t)Dm*Dm];        // straight [m][d]
__device__ __half g_wv [(size_t)Dm*Dm];        // transposed
__device__ __half g_wo [(size_t)Dm*Dm];        // transposed
__device__ __half g_hh [(size_t)Ssup*Bsz*Ff];  // h single fp16
__device__ __half g_yh [(size_t)Ssup*Bsz*Dm];  // y single fp16 (lo dropped)
__device__ __half g_qh [(size_t)Bsz*Dm];
__device__ __half g_zh [(size_t)Hh*Bsz*Dm];    // [h][b][m]
__device__ __half g_oh [(size_t)Bsz*Dm];
__device__ float g_t [(size_t)Hh*Bsz*Dm];      // [h][b][m]

// ---------------- asm helpers (generic-target PTX, sm_80+) ----------------
__device__ __forceinline__ uint32_t smem_u32(const void* p) {
    uint32_t a;
    asm("{ .reg .u64 t; cvta.to.shared.u64 t, %1; cvt.u32.u64 %0, t; }" : "=r"(a) : "l"(p));
    return a;
}
__device__ __forceinline__ void cp16(uint32_t dst, const void* src) {
    asm volatile("cp.async.cg.shared.global [%0], [%1], 16;" :: "r"(dst), "l"(src));
}
#define CP_COMMIT() asm volatile("cp.async.commit_group;" ::: "memory")
#define CP_WAIT(n)  asm volatile("cp.async.wait_group %0;" :: "n"(n) : "memory")
#define LDSM4(r, a) asm volatile("ldmatrix.sync.aligned.m8n8.x4.shared.b16 {%0,%1,%2,%3}, [%4];" \
    : "=r"((r)[0]), "=r"((r)[1]), "=r"((r)[2]), "=r"((r)[3]) : "r"(a))
#define MMA16816(ac, a, b0, b1) \
    asm volatile("mma.sync.aligned.m16n8k16.row.col.f32.f16.f16.f32 " \
        "{%0,%1,%2,%3}, {%4,%5,%6,%7}, {%8,%9}, {%0,%1,%2,%3};" \
        : "+f"((ac)[0]), "+f"((ac)[1]), "+f"((ac)[2]), "+f"((ac)[3]) \
        : "r"((a)[0]), "r"((a)[1]), "r"((a)[2]), "r"((a)[3]), "r"(b0), "r"(b1))

__device__ __forceinline__ float gelu_exact(float x) {
    return 0.5f * x * (1.0f + erff(x * 0.70710678118654752440f));
}
// 16B-chunk swizzle for 128B rows (8 chunks per row): chunk' = chunk ^ (row & 7)
__device__ __forceinline__ uint32_t swz(int row, int c16) {
    return (uint32_t)(row * 8 + (c16 ^ (row & 7))) * 16u;
}

// ---------------- conversion / build kernels ----------------
__global__ void half_arr(const float* __restrict__ in, __half* __restrict__ o, size_t n) {
    size_t i = (size_t)blockIdx.x * blockDim.x + threadIdx.x;
    if (i < n) o[i] = __float2half(in[i]);
}

__global__ __launch_bounds__(256)
void ttile_w(const float* __restrict__ wq, const float* __restrict__ wv,
             const float* __restrict__ wo,
             __half* __restrict__ oq, __half* __restrict__ ov, __half* __restrict__ oo)
{
    __shared__ float tile[32][33];
    const float* w = blockIdx.z == 0 ? wq : (blockIdx.z == 1 ? wv : wo);
    __half* o      = blockIdx.z == 0 ? oq : (blockIdx.z == 1 ? ov : oo);
    const int bx = blockIdx.x * 32, by = blockIdx.y * 32;
    const int tx = threadIdx.x & 31, ty = threadIdx.x >> 5;  // 32x8
#pragma unroll
    for (int j = 0; j < 4; j++)
        tile[ty + j * 8][tx] = w[(size_t)(by + ty + j * 8) * Dm + bx + tx];
    __syncthreads();
#pragma unroll
    for (int j = 0; j < 4; j++)
        o[(size_t)(bx + ty + j * 8) * Dm + by + tx] = __float2half(tile[tx][ty + j * 8]);
}

#define W1_SMEM ((16*32*17 + 512) * 4)
__global__ __launch_bounds__(256)
void build_w1_tiled(const float* __restrict__ g1a, const float* __restrict__ g1b,
                    __half* __restrict__ o)
{
    extern __shared__ float dsm[];
    float* Bs = dsm;                 // [(r*32+i2)*17 + o2l]
    float* As = dsm + 16 * 32 * 17;  // [i1][r]
    const int tid = threadIdx.x;
    const int o1 = blockIdx.x, q = blockIdx.y, s = blockIdx.z;

    for (int idx = tid; idx < 8192; idx += 256) {
        int r = idx >> 9, i2 = (idx >> 4) & 31, o2l = idx & 15;
        Bs[(r * 32 + i2) * 17 + o2l] =
            g1b[(size_t)s * 32768 + (size_t)r * 2048 + i2 * 64 + q * 16 + o2l];
    }
    for (int idx = tid; idx < 512; idx += 256) {
        int i1 = idx >> 4, r = idx & 15;
        As[idx] = g1a[(((size_t)s * 32 + i1) * 64 + o1) * 16 + r];
    }
    __syncthreads();

    const size_t ob = ((size_t)s * Ff + (size_t)o1 * 64 + q * 16) * Dm;
#pragma unroll 4
    for (int it = 0; it < 64; it++) {
        int idx = tid + (it << 8);
        int o2l = idx >> 10, d = idx & 1023;
        int i1 = d >> 5, i2 = d & 31;
        const float* ap = As + i1 * 16;
        const float* bp = Bs + i2 * 17 + o2l;
        float sum = 0.f;
#pragma unroll
        for (int r = 0; r < 16; r++) sum += ap[r] * bp[r * 544];
        o[ob + (size_t)o2l * Dm + d] = __float2half(sum);
    }
}

#define W2_SMEM ((16*16*33 + 512) * 4)
__global__ __launch_bounds__(256)
void build_w2_tiled(const float* __restrict__ g2a, const float* __restrict__ g2b,
                    __half* __restrict__ o)
{
    extern __shared__ float dsm[];
    float* Bs = dsm;                 // [(r*16+o2l)*33 + i2]
    float* As = dsm + 16 * 16 * 33;  // [i1][r]
    const int tid = threadIdx.x;
    const int o1 = blockIdx.x, q = blockIdx.y, s = blockIdx.z;

    for (int idx = tid; idx < 8192; idx += 256) {
        int r = idx >> 9, o2l = (idx >> 5) & 15, i2 = idx & 31;
        Bs[(r * 16 + o2l) * 33 + i2] =
            g2b[(size_t)s * 32768 + (size_t)r * 2048 + (q * 16 + o2l) * 32 + i2];
    }
    for (int idx = tid; idx < 512; idx += 256) {
        int i1 = idx >> 4, r = idx & 15;
        As[idx] = g2a[(((size_t)s * 64 + o1) * 32 + i1) * 16 + r];
    }
    __syncthreads();

    const size_t ob = (size_t)s * Dm * Ff + (size_t)o1 * 64 + q * 16;
#pragma unroll 4
    for (int it = 0; it < 64; it++) {
        int idx = tid + (it << 8);
        int d = idx >> 4, o2l = idx & 15;
        int i1 = d >> 5, i2 = d & 31;
        const float* ap = As + i1 * 16;
        const float* bp = Bs + o2l * 33 + i2;
        float sum = 0.f;
#pragma unroll
        for (int r = 0; r < 16; r++) sum += ap[r] * bp[r * 528];
        o[ob + (size_t)d * Ff + o2l] = __float2half(sum);
    }
}

// ---------------- fp16 HMMA GEMM body (BK=64) ----------------
// EPI: 1 gelu+single, 2 bias+fp32, 4 fp32, 5 bias+single, 6 plain single
template <int EPI, int XA, int BNT>
__device__ __forceinline__
void gemm_body(const __half* __restrict__ Ah, const __half* __restrict__ Al,
               int lda, size_t aBS,
               const __half* __restrict__ Bh, int ldb, size_t bBS,
               int K, int ldc, size_t cBS,
               float* __restrict__ Cf,
               __half* __restrict__ Chi,
               const float* __restrict__ bias, size_t biasBS)
{
    constexpr uint32_t B_Bt = BNT * BK * 2;
    constexpr uint32_t STG  = XA * A_B + B_Bt;
    constexpr int P = BNT / 64;
    extern __shared__ char smem[];
    const uint32_t sb = smem_u32(smem);
    const int tid = threadIdx.x, wid = tid >> 5, lane = tid & 31;
    const int zz = blockIdx.z;
    const int m0 = blockIdx.y * BM, n0 = blockIdx.x * BNT;

    const __half* pAh = Ah + (size_t)zz * aBS;
    const __half* pAl = (XA == 2) ? Al + (size_t)zz * aBS : nullptr;
    const __half* pBh = Bh + (size_t)zz * bBS;

    const int mwarp = (wid & 1) * 64;
    const int nwarp = (wid >> 1) * (BNT / 4);

    float acc[4][2 * P][4];
#pragma unroll
    for (int i = 0; i < 4; i++)
#pragma unroll
        for (int j = 0; j < 2 * P; j++)
#pragma unroll
            for (int c = 0; c < 4; c++) acc[i][j][c] = 0.f;

    const int nk = K / BK;
    const int fr = tid >> 3, fc = tid & 7;

    auto fill = [&](int kt, int st) {
        const int k0 = kt * BK;
        const uint32_t base = sb + st * STG;
#pragma unroll
        for (int i = 0; i < 4; i++) {
            int r = fr + i * 32;
            cp16(base + swz(r, fc), pAh + (size_t)(m0 + r) * lda + k0 + fc * 8);
            if (XA == 2)
                cp16(base + A_B + swz(r, fc), pAl + (size_t)(m0 + r) * lda + k0 + fc * 8);
        }
#pragma unroll
        for (int i = 0; i < BNT / 32; i++) {
            int r = fr + i * 32;
            cp16(base + XA*A_B + swz(r, fc), pBh + (size_t)(n0 + r) * ldb + k0 + fc * 8);
        }
        CP_COMMIT();
    };

    fill(0, 0);
    if (nk > 1) fill(1, 1);

    const int ra = lane & 15, ca = lane >> 4;
    const int gb = lane >> 3, rb = lane & 7;

    for (int kt = 0; kt < nk; kt++) {
        if (kt + 1 >= nk) { CP_WAIT(0); } else { CP_WAIT(1); }
        __syncthreads();
        if (kt + 2 < nk) fill(kt + 2, (kt + 2) % NST);

        const uint32_t base = sb + (kt % NST) * STG;
        const uint32_t sAh = base, sAl = base + A_B;
        const uint32_t sBh = base + XA * A_B;

#pragma unroll
        for (int kk = 0; kk < 4; kk++) {
            uint32_t ah[4][4], al[4][4];
#pragma unroll
            for (int mt = 0; mt < 4; mt++) {
                uint32_t off = swz(mwarp + mt * 16 + ra, kk * 2 + ca);
                LDSM4(ah[mt], sAh + off);
                if (XA == 2) LDSM4(al[mt], sAl + off);
            }
#pragma unroll
            for (int p = 0; p < P; p++) {
                uint32_t bh[4];
                uint32_t off = swz(nwarp + p * 16 + (gb & 1) * 8 + rb, kk * 2 + (gb >> 1));
                LDSM4(bh, sBh + off);
#pragma unroll
                for (int mt = 0; mt < 4; mt++) {
                    MMA16816(acc[mt][2*p],   ah[mt], bh[0], bh[2]);
                    MMA16816(acc[mt][2*p+1], ah[mt], bh[1], bh[3]);
                    if (XA == 2) {
                        MMA16816(acc[mt][2*p],   al[mt], bh[0], bh[2]);
                        MMA16816(acc[mt][2*p+1], al[mt], bh[1], bh[3]);
                    }
                }
            }
        }
    }

    float* Cfp = Cf ? Cf + (size_t)zz * cBS : nullptr;
    __half* Chp = Chi ? Chi + (size_t)zz * cBS : nullptr;
    const float* bp = bias ? bias + (size_t)zz * biasBS : nullptr;
    const int g4 = lane >> 2, q2 = (lane & 3) * 2;

#pragma unroll
    for (int mt = 0; mt < 4; mt++) {
#pragma unroll
        for (int nt = 0; nt < 2 * P; nt++) {
            int r0 = m0 + mwarp + mt * 16 + g4;
            int c  = n0 + nwarp + nt * 8 + q2;
#pragma unroll
            for (int half = 0; half < 2; half++) {
                int rr = r0 + half * 8;
                float v0 = acc[mt][nt][half * 2 + 0];
                float v1 = acc[mt][nt][half * 2 + 1];
                size_t off = (size_t)rr * ldc + c;
                if (EPI == 2) {
                    *reinterpret_cast<float2*>(&Cfp[off]) =
                        make_float2(v0 + bp[c], v1 + bp[c + 1]);
                } else if (EPI == 4) {
                    *reinterpret_cast<float2*>(&Cfp[off]) = make_float2(v0, v1);
                } else if (EPI == 1) {
                    __half2 h2;
                    h2.x = __float2half(gelu_exact(v0));
                    h2.y = __float2half(gelu_exact(v1));
                    *reinterpret_cast<__half2*>(&Chp[off]) = h2;
                } else if (EPI == 5) {
                    __half2 h2;
                    h2.x = __float2half(v0 + bp[c]);
                    h2.y = __float2half(v1 + bp[c + 1]);
                    *reinterpret_cast<__half2*>(&Chp[off]) = h2;
                } else {  // EPI == 6: plain single fp16
                    __half2 h2;
                    h2.x = __float2half(v0);
                    h2.y = __float2half(v1);
                    *reinterpret_cast<__half2*>(&Chp[off]) = h2;
                }
            }
        }
    }
}

// small-GEMM shell (BN=256, occ1)
template <int EPI, int XA>
__global__ __launch_bounds__(256, 1)
void mma_gemm(const __half* __restrict__ Ah, const __half* __restrict__ Al,
              int lda, size_t aBS,
              const __half* __restrict__ Bh, int ldb, size_t bBS,
              int K, int ldc, size_t cBS,
              float* __restrict__ Cf, __half* __restrict__ Chi,
              const float* __restrict__ bias, size_t biasBS)
{
    gemm_body<EPI, XA, 256>(Ah, Al, lda, aBS, Bh, ldb, bBS, K, ldc, cBS,
                            Cf, Chi, bias, biasBS);
}

// FFN shell (BN=128, occ2) — proven best config
template <int EPI, int XA>
__global__ __launch_bounds__(256, 2)
void mma_gemm2(const __half* __restrict__ Ah, const __half* __restrict__ Al,
               int lda, size_t aBS,
               const __half* __restrict__ Bh, int ldb, size_t bBS,
               int K, int ldc, size_t cBS,
               float* __restrict__ Cf, __half* __restrict__ Chi,
               const float* __restrict__ bias, size_t biasBS)
{
    gemm_body<EPI, XA, 128>(Ah, Al, lda, aBS, Bh, ldb, bBS, K, ldc, cBS,
                            Cf, Chi, bias, biasBS);
}

// ---------------- attention collapse: scores, softmax, z ----------------
// pointers may be pre-offset by a half-batch (offD); indexing uses full Bsz strides
__global__ __launch_bounds__(256)
void attn_collapse(const __half* __restrict__ qh,
                   const float* __restrict__ t,
                   const __half* __restrict__ yh,
                   const float* __restrict__ bk,
                   __half* __restrict__ zh)
{
    const int b = blockIdx.x, tid = threadIdx.x;
    const int wid = tid >> 5, lane = tid & 31;
    __shared__ float ys[Ssup][Dm];
    __shared__ float sc[16], qb[Hh], attn[16];

#pragma unroll
    for (int it = 0; it < 8; it++) {
        int idx = tid + it * 256;
        int s = idx >> 9, mm = idx & 511;
        size_t g = ((size_t)s * Bsz + b) * Dm + mm * 2;
        __half2 h2 = *reinterpret_cast<const __half2*>(&yh[g]);
        ys[s][mm * 2]     = __half2float(h2.x);
        ys[s][mm * 2 + 1] = __half2float(h2.y);
    }
    if (wid < Hh) {
        float sum = 0.f;
        for (int j = lane; j < HD; j += 32) {
            size_t g = (size_t)b * Dm + wid * HD + j;
            sum = fmaf(__half2float(qh[g]), bk[wid * HD + j], sum);
        }
#pragma unroll
        for (int o = 16; o; o >>= 1) sum += __shfl_xor_sync(0xffffffffu, sum, o);
        if (lane == 0) qb[wid] = sum;
    }
    __syncthreads();

#pragma unroll
    for (int i = 0; i < 2; i++) {
        int p = wid * 2 + i;
        int h = p >> 2, s = p & 3;
        const float* tp = t + ((size_t)h * Bsz + b) * Dm;
        float sum = 0.f;
        for (int m = lane; m < Dm; m += 32) sum = fmaf(ys[s][m], tp[m], sum);
#pragma unroll
        for (int o = 16; o; o >>= 1) sum += __shfl_xor_sync(0xffffffffu, sum, o);
        if (lane == 0) sc[p] = sum;
    }
    __syncthreads();

    if (tid < Hh) {
        int h = tid;
        float s0 = (sc[h*4+0] + qb[h]) * 0.0625f;
        float s1 = (sc[h*4+1] + qb[h]) * 0.0625f;
        float s2 = (sc[h*4+2] + qb[h]) * 0.0625f;
        float s3 = (sc[h*4+3] + qb[h]) * 0.0625f;
        float m = fmaxf(fmaxf(s0, s1), fmaxf(s2, s3));
        float e0 = expf(s0-m), e1 = expf(s1-m), e2 = expf(s2-m), e3 = expf(s3-m);
        float inv = 1.f / (e0 + e1 + e2 + e3);
        attn[h*4+0] = e0*inv; attn[h*4+1] = e1*inv;
        attn[h*4+2] = e2*inv; attn[h*4+3] = e3*inv;
    }
    __syncthreads();

#pragma unroll
    for (int it = 0; it < 8; it++) {
        int idx = tid + it * 256;
        int h = idx >> 9, mm = idx & 511;
        int m = mm * 2;
        float a0 = attn[h*4+0], a1 = attn[h*4+1], a2 = attn[h*4+2], a3 = attn[h*4+3];
        float z0 = a0*ys[0][m]   + a1*ys[1][m]   + a2*ys[2][m]   + a3*ys[3][m];
        float z1 = a0*ys[0][m+1] + a1*ys[1][m+1] + a2*ys[2][m+1] + a3*ys[3][m+1];
        size_t g = ((size_t)h * Bsz + b) * Dm + m;
        __half2 z2;
        z2.x = __float2half(z0);
        z2.y = __float2half(z1);
        *reinterpret_cast<__half2*>(&zh[g]) = z2;
    }
}

// ---------------- launch ----------------
extern "C" void kernel_launch(void* const* d_in, const int* in_sizes, int n_in,
                              void* d_out, int out_size)
{
    const float* x   = (const float*)d_in[0];
    const float* g1a = (const float*)d_in[1];
    const float* g1b = (const float*)d_in[2];
    const float* g2a = (const float*)d_in[3];
    const float* g2b = (const float*)d_in[4];
    const float* wq  = (const float*)d_in[5];
    const float* bq  = (const float*)d_in[6];
    const float* wk  = (const float*)d_in[7];
    const float* bk  = (const float*)d_in[8];
    const float* wv  = (const float*)d_in[9];
    const float* bv  = (const float*)d_in[10];
    const float* wo  = (const float*)d_in[11];
    const float* bo  = (const float*)d_in[12];
    float* out = (float*)d_out;

    __half *xh,*w1,*w2,*wqp,*wk2,*wvp,*wop,*hh,*yh,*qh,*zh,*oh;
    float *t;
    cudaGetSymbolAddress((void**)&xh, g_xh);
    cudaGetSymbolAddress((void**)&w1, g_w1);   cudaGetSymbolAddress((void**)&w2, g_w2);
    cudaGetSymbolAddress((void**)&wqp, g_wq);  cudaGetSymbolAddress((void**)&wk2, g_wk2);
    cudaGetSymbolAddress((void**)&wvp, g_wv);  cudaGetSymbolAddress((void**)&wop, g_wo);
    cudaGetSymbolAddress((void**)&hh, g_hh);
    cudaGetSymbolAddress((void**)&yh, g_yh);
    cudaGetSymbolAddress((void**)&qh, g_qh);
    cudaGetSymbolAddress((void**)&zh, g_zh);
    cudaGetSymbolAddress((void**)&oh, g_oh);
    cudaGetSymbolAddress((void**)&t, g_t);

    const int SM1b = NST * (A_B + 128 * BK * 2);     // 98304  (FFN, BN=128, occ2)
    const int SM1  = NST * (A_B + 256 * BK * 2);     // 147456 (small, BN=256)
    cudaFuncSetAttribute((const void*)mma_gemm2<1,1>, cudaFuncAttributeMaxDynamicSharedMemorySize, SM1b);
    cudaFuncSetAttribute((const void*)mma_gemm2<6,1>, cudaFuncAttributeMaxDynamicSharedMemorySize, SM1b);
    cudaFuncSetAttribute((const void*)mma_gemm<5,1>,  cudaFuncAttributeMaxDynamicSharedMemorySize, SM1);
    cudaFuncSetAttribute((const void*)mma_gemm<4,1>,  cudaFuncAttributeMaxDynamicSharedMemorySize, SM1);
    cudaFuncSetAttribute((const void*)mma_gemm<2,1>,  cudaFuncAttributeMaxDynamicSharedMemorySize, SM1);
    cudaFuncSetAttribute((const void*)build_w1_tiled, cudaFuncAttributeMaxDynamicSharedMemorySize, W1_SMEM);
    cudaFuncSetAttribute((const void*)build_w2_tiled, cudaFuncAttributeMaxDynamicSharedMemorySize, W2_SMEM);

    const size_t sBD = (size_t)Bsz * Dm, sBF = (size_t)Bsz * Ff;
    const size_t sDD = (size_t)Dm * Dm, sFD = (size_t)Ff * Dm;
    const size_t offH = (size_t)BHALF * Ff;
    const size_t offD = (size_t)BHALF * Dm;

    // streams: s1 = q/t chain, s2 = build_w2, s3 = tail upper-half. Fallback: all on 0.
    cudaStream_t s1 = 0, s2 = 0, s3 = 0;
    cudaEvent_t evX = 0, evJ = 0, evW2 = 0, evY0 = 0, evT0 = 0;
    bool forked = (cudaStreamCreateWithFlags(&s1, cudaStreamNonBlocking) == cudaSuccess);
    if (forked && cudaStreamCreateWithFlags(&s2, cudaStreamNonBlocking) != cudaSuccess) {
        cudaStreamDestroy(s1); s1 = 0; forked = false;
    }
    if (forked && cudaStreamCreateWithFlags(&s3, cudaStreamNonBlocking) != cudaSuccess) {
        cudaStreamDestroy(s1); cudaStreamDestroy(s2); s1 = s2 = 0; forked = false;
    }
    if (forked && (cudaEventCreateWithFlags(&evX, cudaEventDisableTiming) != cudaSuccess ||
                   cudaEventCreateWithFlags(&evJ, cudaEventDisableTiming) != cudaSuccess ||
                   cudaEventCreateWithFlags(&evW2, cudaEventDisableTiming) != cudaSuccess ||
                   cudaEventCreateWithFlags(&evY0, cudaEventDisableTiming) != cudaSuccess ||
                   cudaEventCreateWithFlags(&evT0, cudaEventDisableTiming) != cudaSuccess)) {
        if (evX) cudaEventDestroy(evX);
        if (evJ) cudaEventDestroy(evJ);
        if (evW2) cudaEventDestroy(evW2);
        if (evY0) cudaEventDestroy(evY0);
        if (evT0) cudaEventDestroy(evT0);
        cudaStreamDestroy(s1); cudaStreamDestroy(s2); cudaStreamDestroy(s3);
        s1 = s2 = s3 = 0; evX = evJ = evW2 = evY0 = evT0 = 0; forked = false;
    }

    // main: x -> fp16
    half_arr<<<(Bsz * Dm) / 256, 256>>>(x, xh, sBD);
    if (forked) {
        cudaEventRecord(evX, 0);
        cudaStreamWaitEvent(s1, evX, 0);
        cudaStreamWaitEvent(s2, evX, 0);
        cudaStreamWaitEvent(s3, evX, 0);
    }

    // s2: w2 build
    build_w2_tiled<<<dim3(64, 4, Ssup), 256, W2_SMEM, s2>>>(g2a, g2b, w2);
    if (forked) cudaEventRecord(evW2, s2);

    // s1: attention-path weight preps, then q -> t
    ttile_w<<<dim3(32, 32, 3), 256, 0, s1>>>(wq, wv, wo, wqp, wvp, wop);
    half_arr<<<(Dm * Dm) / 256, 256, 0, s1>>>(wk, wk2, sDD);
    mma_gemm<5,1><<<dim3(Dm/256, Bsz/BM, 1), 256, SM1, s1>>>(
        xh, nullptr, Dm, 0, wqp, Dm, 0, Dm, Dm, 0,
        nullptr, qh, bq, 0);
    mma_gemm<4,1><<<dim3(Dm/256, Bsz/BM, Hh), 256, SM1, s1>>>(
        qh, nullptr, Dm, HD, wk2, Dm, HD, HD, Dm, sBD,
        t, nullptr, nullptr, 0);
    if (forked) cudaEventRecord(evJ, s1);

    // main: w1 build, FFN1 (full B, BK=64 occ2)
    build_w1_tiled<<<dim3(64, 4, Ssup), 256, W1_SMEM>>>(g1a, g1b, w1);
    mma_gemm2<1,1><<<dim3(Ff/128, Bsz/BM, Ssup), 256, SM1b>>>(
        xh, nullptr, Dm, 0, w1, Dm, sFD, Dm, Ff, sBF,
        nullptr, hh, nullptr, 0);

    // main: FFN2 UPPER half first (rows [BHALF, Bsz)) — matches the s3 tail below
    if (forked) cudaStreamWaitEvent(0, evW2, 0);
    mma_gemm2<6,1><<<dim3(Dm/128, BHALF/BM, Ssup), 256, SM1b>>>(
        hh + offH, nullptr, Ff, sBF, w2, Ff, (size_t)Dm*Ff, Ff, Dm, sBD,
        nullptr, yh + offD, nullptr, 0);
    if (forked) cudaEventRecord(evY0, 0);

    // s3: tail for the UPPER half (runs beside FFN2 lower half)
    if (forked) {
        cudaStreamWaitEvent(s3, evY0, 0);
        cudaStreamWaitEvent(s3, evJ, 0);
    }
    attn_collapse<<<BHALF, 256, 0, s3>>>(qh + offD, t + offD, yh + offD, bk, zh + offD);
    mma_gemm<5,1><<<dim3(1, BHALF/BM, Hh), 256, SM1, s3>>>(
        zh + offD, nullptr, Dm, sBD, wvp, Dm, (size_t)HD*Dm, Dm, Dm, (size_t)HD,
        nullptr, oh + offD, bv, HD);
    mma_gemm<2,1><<<dim3(Dm/256, BHALF/BM, 1), 256, SM1, s3>>>(
        oh + offD, nullptr, Dm, 0, wop, Dm, 0, Dm, Dm, 0,
        out + offD, nullptr, bo, 0);
    if (forked) cudaEventRecord(evT0, s3);

    // main: FFN2 LOWER half (rows [0, BHALF))
    mma_gemm2<6,1><<<dim3(Dm/128, BHALF/BM, Ssup), 256, SM1b>>>(
        hh, nullptr, Ff, sBF, w2, Ff, (size_t)Dm*Ff, Ff, Dm, sBD,
        nullptr, yh, nullptr, 0);

    // main: tail for the LOWER half
    if (forked) cudaStreamWaitEvent(0, evJ, 0);
    attn_collapse<<<BHALF, 256>>>(qh, t, yh, bk, zh);
    mma_gemm<5,1><<<dim3(1, BHALF/BM, Hh), 256, SM1>>>(
        zh, nullptr, Dm, sBD, wvp, Dm, (size_t)HD*Dm, Dm, Dm, (size_t)HD,
        nullptr, oh, bv, HD);
    mma_gemm<2,1><<<dim3(Dm/256, BHALF/BM, 1), 256, SM1>>>(
        oh, nullptr, Dm, 0, wop, Dm, 0, Dm, Dm, 0,
        out, nullptr, bo, 0);

    // join s3 back into origin before capture ends
    if (forked) cudaStreamWaitEvent(0, evT0, 0);

    if (forked) {
        cudaEventDestroy(evX);
        cudaEventDestroy(evJ);
        cudaEventDestroy(evW2);
        cudaEventDestroy(evY0);
        cudaEventDestroy(evT0);
        cudaStreamDestroy(s1);
        cudaStreamDestroy(s2);
        cudaStreamDestroy(s3);
    }
}